// round 16
// baseline (speedup 1.0000x reference)
#include <cuda_runtime.h>
#include <cuda_bf16.h>
#include <cuda_fp16.h>
#include <math.h>
#include <stdint.h>

// ---------------- problem constants ----------------
#define BB    4
#define CCH   256
#define C2H   128
#define HO    63
#define WO    63
#define NPIX  (HO*WO)      // 3969
#define XLD   3972         // padded stride for xp/o2
#define XB    3976         // padded fp16 stride (16B-aligned rows)
#define YB    3976         // padded fp16 stride for y raw-view rows
#define MLD   4096         // fp16 m-stride for g (mult of 64)
#define HIN   128
#define WIN   128
#define EPSV  1e-5f
#define PAD   32768

// ---------------- scratch (device globals; zero-initialized) ----------------
__device__ __align__(256) float  g_xp [BB*CCH*XLD + PAD];   // residual fp32
__device__ __align__(256) __half g_o2h[BB*CCH*XLD + PAD];   // pre-BN fp16
__device__ float g_mean[CCH];
__device__ float g_rstd[CCH];

__device__ __align__(256) __half g_xph [BB*CCH*XB + PAD];  // xp fp16 (C-major rows)
__device__ __align__(256) __half g_thw [128*256];          // fp16 weights
__device__ __align__(256) __half g_phw [128*256];
__device__ __align__(256) __half g_gw  [128*256];
__device__ __align__(256) __half g_yw  [256*128];

__device__ __align__(256) __half g_th_h[BB*NPIX*C2H + PAD];   // theta (B,N,C2)
__device__ __align__(256) __half g_ph_h[BB*NPIX*C2H + PAD];   // phi   (B,M,C2)
__device__ __align__(256) __half g_gc_h[BB*C2H*MLD + PAD];    // g (B,C2,MLD) tail=0
__device__ __align__(256) __half g_yv_h[BB*C2H*YB + PAD];     // y raw-view (B,C2,m)

// ---------------- common asm helpers ----------------
#define MMAH16816(d, a, b)                                                  \
    asm volatile("mma.sync.aligned.m16n8k16.row.col.f32.f16.f16.f32 "       \
                 "{%0,%1,%2,%3},{%4,%5,%6,%7},{%8,%9},{%0,%1,%2,%3};"       \
                 : "+f"((d)[0]), "+f"((d)[1]), "+f"((d)[2]), "+f"((d)[3])   \
                 : "r"((a)[0]), "r"((a)[1]), "r"((a)[2]), "r"((a)[3]),      \
                   "r"((b)[0]), "r"((b)[1]))

#define LDSM4(r, p)                                                         \
    asm volatile("ldmatrix.sync.aligned.m8n8.x4.shared.b16 "                \
                 "{%0,%1,%2,%3}, [%4];"                                     \
                 : "=r"((r)[0]), "=r"((r)[1]), "=r"((r)[2]), "=r"((r)[3])   \
                 : "r"(p))

#define LDSM4T(r, p)                                                        \
    asm volatile("ldmatrix.sync.aligned.m8n8.x4.trans.shared.b16 "          \
                 "{%0,%1,%2,%3}, [%4];"                                     \
                 : "=r"((r)[0]), "=r"((r)[1]), "=r"((r)[2]), "=r"((r)[3])   \
                 : "r"(p))

#define CPA16(dst, src)                                                     \
    asm volatile("cp.async.cg.shared.global [%0], [%1], 16;"                \
                 :: "r"(dst), "l"(src) : "memory")

__device__ __forceinline__ uint32_t pk_h2(float x, float y) {
    __half2 h = __floats2half2_rn(x, y);
    return *(uint32_t*)&h;
}

// ---------------- 3x3/2 VALID max pool (+ fp16 emit) ----------------
__global__ void pool_k(const float* __restrict__ x) {
    int idx = blockIdx.x * blockDim.x + threadIdx.x;
    if (idx >= BB*CCH*NPIX) return;
    int n  = idx % NPIX;
    int bc = idx / NPIX;
    int ow = n % WO, oh = n / WO;
    const float* p = x + (size_t)bc * (HIN*WIN) + (oh*2) * WIN + (ow*2);
    float m = -INFINITY;
    #pragma unroll
    for (int i = 0; i < 3; i++) {
        m = fmaxf(m, p[i*WIN + 0]);
        m = fmaxf(m, p[i*WIN + 1]);
        m = fmaxf(m, p[i*WIN + 2]);
    }
    g_xp[(size_t)bc * XLD + n] = m;
    g_xph[(size_t)bc * XB + n] = __float2half(m);
}

// ---------------- weight fp16 prep ----------------
__global__ void wsplit_k(const float* __restrict__ thW, const float* __restrict__ phW,
                         const float* __restrict__ gW,  const float* __restrict__ yW) {
    int idx = blockIdx.x * blockDim.x + threadIdx.x;
    if (idx >= 4*32768) return;
    int arr = idx >> 15, off = idx & 32767;
    const float* s = (arr == 0) ? thW : (arr == 1) ? phW : (arr == 2) ? gW : yW;
    __half v = __float2half(s[off]);
    if      (arr == 0) g_thw[off] = v;
    else if (arr == 1) g_phw[off] = v;
    else if (arr == 2) g_gw [off] = v;
    else               g_yw [off] = v;
}

// ================ single-phase fp16 TN MMA for projections / outproj ================
#define PJ_SW  144
#define PJ_SX  272
#define PJ_WB  (128*PJ_SW)
#define PJ_XTB (64*PJ_SX)
#define PJ_STG (PJ_WB + PJ_XTB)
#define PJ_SMEM (2*PJ_STG)

__global__ __launch_bounds__(256) void projmma_k() {
    extern __shared__ __align__(256) char smem[];
    uint32_t sb = (uint32_t)__cvta_generic_to_shared(smem);
    int t = threadIdx.x, lane = t & 31, wid = t >> 5;
    int b = blockIdx.z, w = blockIdx.y;
    int j0 = blockIdx.x * 128;

    const __half* W  = (w == 0) ? g_thw : (w == 1) ? g_phw : g_gw;
    const __half* Xp = g_xph + (size_t)b * CCH * XB;

    int gq = lane >> 2, tg = lane & 3;
    int a_ro = (lane & 7) + ((lane >> 3) & 1) * 8;
    int a_co = (lane >> 4) * 8;
    int trow = (lane & 7) + ((lane >> 3) & 1) * 8;
    int tcol = (lane >> 4) * 8;

    float acc[16][4];
    #pragma unroll
    for (int fj = 0; fj < 16; fj++)
        #pragma unroll
        for (int e = 0; e < 4; e++) acc[fj][e] = 0.f;

    const int TOT = 4;
    auto issue = [&](int s) {
        int k0 = s * 64;
        uint32_t stg = sb + (s & 1) * PJ_STG;
        #pragma unroll
        for (int it = 0; it < 4; it++) {
            int cid = t + it * 256;
            int r = cid >> 3, q = cid & 7;
            CPA16(stg + r * PJ_SW + q * 16, W + r * 256 + k0 + q * 8);
        }
        #pragma unroll
        for (int it = 0; it < 4; it++) {
            int cid = t + it * 256;
            int r = cid >> 4, q = cid & 15;
            CPA16(stg + PJ_WB + r * PJ_SX + q * 16,
                  Xp + (size_t)(k0 + r) * XB + j0 + q * 8);
        }
        asm volatile("cp.async.commit_group;" ::: "memory");
    };
    issue(0);

    for (int s = 0; s < TOT; s++) {
        if (s + 1 < TOT) {
            issue(s + 1);
            asm volatile("cp.async.wait_group 1;" ::: "memory");
        } else {
            asm volatile("cp.async.wait_group 0;" ::: "memory");
        }
        __syncthreads();
        uint32_t stg = sb + (s & 1) * PJ_STG;
        uint32_t aB = stg + (wid * 16 + a_ro) * PJ_SW + a_co * 2;
        uint32_t xB = stg + PJ_WB + trow * PJ_SX + tcol * 2;
        #pragma unroll
        for (int k16 = 0; k16 < 4; k16++) {
            uint32_t a[4];
            LDSM4(a, aB + k16 * 32);
            #pragma unroll
            for (int jb = 0; jb < 8; jb++) {
                uint32_t r[4];
                LDSM4T(r, xB + k16 * 16 * PJ_SX + jb * 32);
                MMAH16816(acc[2*jb],     a, r);
                MMAH16816(acc[2*jb + 1], a, r + 2);
            }
        }
        __syncthreads();
    }

    if (w < 2) {
        float* stage = (float*)smem;
        int r0 = wid * 16 + gq, r1 = r0 + 8;
        #pragma unroll
        for (int fj = 0; fj < 16; fj++) {
            int c = fj * 8 + tg * 2;
            *(float2*)&stage[r0 * 132 + c] = make_float2(acc[fj][0], acc[fj][1]);
            *(float2*)&stage[r1 * 132 + c] = make_float2(acc[fj][2], acc[fj][3]);
        }
        __syncthreads();
        int j = t >> 1, half = t & 1;
        int n = j0 + j;
        if (n < NPIX) {
            size_t base = (size_t)(b * NPIX + n) * C2H + half * 64;
            __half* TH = ((w == 0) ? g_th_h : g_ph_h) + base;
            uint32_t hb[32];
            #pragma unroll
            for (int i = 0; i < 64; i += 2) {
                float v0 = stage[(half * 64 + i)     * 132 + j];
                float v1 = stage[(half * 64 + i + 1) * 132 + j];
                hb[i >> 1] = pk_h2(v0, v1);
            }
            #pragma unroll
            for (int u = 0; u < 8; u++)
                ((uint4*)TH)[u] = ((uint4*)hb)[u];
        }
    } else {
        int i0r = wid * 16 + gq;
        #pragma unroll
        for (int fj = 0; fj < 16; fj++) {
            int jj = j0 + fj * 8 + tg * 2;
            #pragma unroll
            for (int h = 0; h < 2; h++) {
                int i = i0r + h * 8;
                float v0 = acc[fj][2*h], v1 = acc[fj][2*h + 1];
                size_t base = (size_t)(b * C2H + i) * MLD + jj;
                if (jj + 1 < NPIX)
                    *(uint32_t*)(g_gc_h + base) = pk_h2(v0, v1);
                else if (jj < NPIX)
                    g_gc_h[base] = __float2half(v0);
            }
        }
    }
}

__global__ __launch_bounds__(256) void opmma_k() {
    extern __shared__ __align__(256) char smem[];
    uint32_t sb = (uint32_t)__cvta_generic_to_shared(smem);
    int t = threadIdx.x, lane = t & 31, wid = t >> 5;
    int b = blockIdx.z;
    int o0 = blockIdx.y * 128;
    int j0 = blockIdx.x * 128;

    const __half* Xp = g_yv_h + (size_t)b * C2H * YB;

    int gq = lane >> 2, tg = lane & 3;
    int a_ro = (lane & 7) + ((lane >> 3) & 1) * 8;
    int a_co = (lane >> 4) * 8;
    int trow = (lane & 7) + ((lane >> 3) & 1) * 8;
    int tcol = (lane >> 4) * 8;

    float acc[16][4];
    #pragma unroll
    for (int fj = 0; fj < 16; fj++)
        #pragma unroll
        for (int e = 0; e < 4; e++) acc[fj][e] = 0.f;

    const int TOT = 2;
    auto issue = [&](int s) {
        int k0 = s * 64;
        uint32_t stg = sb + (s & 1) * PJ_STG;
        #pragma unroll
        for (int it = 0; it < 4; it++) {
            int cid = t + it * 256;
            int r = cid >> 3, q = cid & 7;
            CPA16(stg + r * PJ_SW + q * 16, g_yw + (o0 + r) * 128 + k0 + q * 8);
        }
        #pragma unroll
        for (int it = 0; it < 4; it++) {
            int cid = t + it * 256;
            int r = cid >> 4, q = cid & 15;
            CPA16(stg + PJ_WB + r * PJ_SX + q * 16,
                  Xp + (size_t)(k0 + r) * YB + j0 + q * 8);
        }
        asm volatile("cp.async.commit_group;" ::: "memory");
    };
    issue(0);

    for (int s = 0; s < TOT; s++) {
        if (s + 1 < TOT) {
            issue(s + 1);
            asm volatile("cp.async.wait_group 1;" ::: "memory");
        } else {
            asm volatile("cp.async.wait_group 0;" ::: "memory");
        }
        __syncthreads();
        uint32_t stg = sb + (s & 1) * PJ_STG;
        uint32_t aB = stg + (wid * 16 + a_ro) * PJ_SW + a_co * 2;
        uint32_t xB = stg + PJ_WB + trow * PJ_SX + tcol * 2;
        #pragma unroll
        for (int k16 = 0; k16 < 4; k16++) {
            uint32_t a[4];
            LDSM4(a, aB + k16 * 32);
            #pragma unroll
            for (int jb = 0; jb < 8; jb++) {
                uint32_t r[4];
                LDSM4T(r, xB + k16 * 16 * PJ_SX + jb * 32);
                MMAH16816(acc[2*jb],     a, r);
                MMAH16816(acc[2*jb + 1], a, r + 2);
            }
        }
        __syncthreads();
    }

    int i0r = o0 + wid * 16 + gq;
    #pragma unroll
    for (int fj = 0; fj < 16; fj++) {
        int jj = j0 + fj * 8 + tg * 2;
        #pragma unroll
        for (int h = 0; h < 2; h++) {
            int i = i0r + h * 8;
            size_t base = (size_t)(b * CCH + i) * XLD + jj;
            if (jj + 1 < NPIX)
                *(uint32_t*)(g_o2h + base) = pk_h2(acc[fj][2*h], acc[fj][2*h + 1]);
            else if (jj < NPIX)
                g_o2h[base] = __float2half(acc[fj][2*h]);
        }
    }
}

// ============ fused flash attention: fp16 single-phase score + AV ============
#define TM   64
#define NT   63
#define THRB 272
#define GRB  144
#define SM_TH    0
#define SM_STG   34816
#define ST_PH    0
#define ST_G     17408
#define STG_SZ   35840
#define SMEM_FLASH (SM_STG + 2*STG_SZ)   // 106496

__global__ __launch_bounds__(256, 1) void flash_k() {
    extern __shared__ __align__(256) char smem[];
    uint32_t sb = (uint32_t)__cvta_generic_to_shared(smem);
    int t = threadIdx.x, lane = t & 31, wid = t >> 5;
    int b = blockIdx.y;
    int q0 = blockIdx.x * 128;

    #pragma unroll
    for (int it = 0; it < 8; it++) {
        int cid = t + it * 256;
        int r = cid >> 4, q = cid & 15;
        size_t off = (size_t)(b * NPIX + q0 + r) * C2H + q * 8;
        CPA16(sb + SM_TH + r * THRB + q * 16, g_th_h + off);
    }
    asm volatile("cp.async.commit_group;" ::: "memory");

    auto issue_stage = [&](int s) {
        int m0 = s * TM;
        uint32_t stg = sb + SM_STG + (s & 1) * STG_SZ;
        #pragma unroll
        for (int it = 0; it < 4; it++) {
            int cid = t + it * 256;
            int r = cid >> 4, q = cid & 15;
            size_t off = (size_t)(b * NPIX + m0 + r) * C2H + q * 8;
            CPA16(stg + ST_PH + r * THRB + q * 16, g_ph_h + off);
        }
        #pragma unroll
        for (int it = 0; it < 4; it++) {
            int cid = t + it * 256;
            int r = cid >> 3, q = cid & 7;
            size_t off = (size_t)(b * C2H + r) * MLD + m0 + q * 8;
            CPA16(stg + ST_G + r * GRB + q * 16, g_gc_h + off);
        }
        asm volatile("cp.async.commit_group;" ::: "memory");
    };
    issue_stage(0);

    int gq = lane >> 2, tg = lane & 3;
    int a_ro = (lane & 7) + ((lane >> 3) & 1) * 8;
    int a_co = (lane >> 4) * 8;
    int b_ro = (lane & 7) + ((lane >> 4) & 1) * 8;
    int b_co = ((lane >> 3) & 1) * 8;

    uint32_t thA = sb + SM_TH + (wid * 16 + a_ro) * THRB + a_co * 2;

    float m0r = -INFINITY, m1r = -INFINITY;
    float l0p = 0.f, l1p = 0.f;           // per-thread partial sums (deferred reduce)
    float accy[16][4];
    #pragma unroll
    for (int fc = 0; fc < 16; fc++)
        #pragma unroll
        for (int e = 0; e < 4; e++) accy[fc][e] = 0.f;

    for (int itr = 0; itr < NT; itr++) {
        if (itr + 1 < NT) {
            issue_stage(itr + 1);
            asm volatile("cp.async.wait_group 1;" ::: "memory");
        } else {
            asm volatile("cp.async.wait_group 0;" ::: "memory");
        }
        __syncthreads();
        uint32_t stg = sb + SM_STG + (itr & 1) * STG_SZ;

        // ---- score: single-phase fp16 ----
        float s[8][4];
        #pragma unroll
        for (int fj = 0; fj < 8; fj++)
            #pragma unroll
            for (int e = 0; e < 4; e++) s[fj][e] = 0.f;

        uint32_t bb = stg + ST_PH + b_ro * THRB + b_co * 2;
        #pragma unroll
        for (int k16 = 0; k16 < 8; k16++) {
            uint32_t a[4];
            LDSM4(a, thA + k16 * 32);
            #pragma unroll
            for (int mb = 0; mb < 4; mb++) {
                uint32_t r[4];
                LDSM4(r, bb + mb * 16 * THRB + k16 * 32);
                MMAH16816(s[2*mb],     a, r);
                MMAH16816(s[2*mb + 1], a, r + 2);
            }
        }

        if (itr == NT - 1) {
            int mbase = itr * TM;
            #pragma unroll
            for (int fj = 0; fj < 8; fj++) {
                int c = mbase + fj * 8 + tg * 2;
                if (c     >= NPIX) { s[fj][0] = -INFINITY; s[fj][2] = -INFINITY; }
                if (c + 1 >= NPIX) { s[fj][1] = -INFINITY; s[fj][3] = -INFINITY; }
            }
        }

        // ---- online softmax ----
        float mx0 = -INFINITY, mx1 = -INFINITY;
        #pragma unroll
        for (int fj = 0; fj < 8; fj++) {
            mx0 = fmaxf(mx0, fmaxf(s[fj][0], s[fj][1]));
            mx1 = fmaxf(mx1, fmaxf(s[fj][2], s[fj][3]));
        }
        mx0 = fmaxf(mx0, __shfl_xor_sync(~0u, mx0, 1));
        mx0 = fmaxf(mx0, __shfl_xor_sync(~0u, mx0, 2));
        mx1 = fmaxf(mx1, __shfl_xor_sync(~0u, mx1, 1));
        mx1 = fmaxf(mx1, __shfl_xor_sync(~0u, mx1, 2));

        float mn0 = fmaxf(m0r, mx0), mn1 = fmaxf(m1r, mx1);
        float sc0 = __expf(m0r - mn0), sc1 = __expf(m1r - mn1);
        m0r = mn0; m1r = mn1;

        // warp-vote skip: rescale only if any lane's max changed
        bool need = (sc0 != 1.f) || (sc1 != 1.f);
        if (__any_sync(0xFFFFFFFFu, need)) {
            l0p *= sc0; l1p *= sc1;
            #pragma unroll
            for (int fc = 0; fc < 16; fc++) {
                accy[fc][0] *= sc0; accy[fc][1] *= sc0;
                accy[fc][2] *= sc1; accy[fc][3] *= sc1;
            }
        }

        uint32_t ph0[8], ph1[8];
        #pragma unroll
        for (int fj = 0; fj < 8; fj++) {
            float p0 = __expf(s[fj][0] - mn0);
            float p1 = __expf(s[fj][1] - mn0);
            float p2 = __expf(s[fj][2] - mn1);
            float p3 = __expf(s[fj][3] - mn1);
            l0p += p0 + p1; l1p += p2 + p3;
            ph0[fj] = pk_h2(p0, p1);
            ph1[fj] = pk_h2(p2, p3);
        }

        // ---- AV: single-phase fp16 ----
        {
            uint32_t gb = stg + ST_G + b_ro * GRB + b_co * 2;
            #pragma unroll
            for (int kw = 0; kw < 4; kw++) {
                uint32_t a[4] = { ph0[2*kw], ph1[2*kw], ph0[2*kw+1], ph1[2*kw+1] };
                #pragma unroll
                for (int fc16 = 0; fc16 < 8; fc16++) {
                    uint32_t r[4];
                    LDSM4(r, gb + fc16 * 16 * GRB + kw * 32);
                    MMAH16816(accy[2*fc16],     a, r);
                    MMAH16816(accy[2*fc16 + 1], a, r + 2);
                }
            }
        }
        __syncthreads();
    }

    // ---- deferred l reduction (once) ----
    float l0r = l0p, l1r = l1p;
    l0r += __shfl_xor_sync(~0u, l0r, 1);
    l0r += __shfl_xor_sync(~0u, l0r, 2);
    l1r += __shfl_xor_sync(~0u, l1r, 1);
    l1r += __shfl_xor_sync(~0u, l1r, 2);

    // finalize: y /= l, emit raw-view (c, m) fp16
    float inv0 = 1.f / l0r, inv1 = 1.f / l1r;
    int row0 = q0 + wid * 16 + gq;
    int row1 = row0 + 8;
    auto emit = [&](int n, int cc, float v) {
        if (n >= NPIX) return;
        uint32_t q = (uint32_t)n * 128u + (uint32_t)cc;
        uint32_t c = q / 3969u;
        uint32_t m = q - c * 3969u;
        g_yv_h[(size_t)(b * C2H + c) * YB + m] = __float2half(v);
    };
    #pragma unroll
    for (int fc = 0; fc < 16; fc++) {
        int col = fc * 8 + tg * 2;
        emit(row0, col,     accy[fc][0] * inv0);
        emit(row0, col + 1, accy[fc][1] * inv0);
        emit(row1, col,     accy[fc][2] * inv1);
        emit(row1, col + 1, accy[fc][3] * inv1);
    }
}

// ---------------- BN stats (fp16 input) ----------------
__global__ void bnstats_k() {
    int c = blockIdx.x;
    int t = threadIdx.x;
    __shared__ double s1[256];
    __shared__ double s2[256];
    double a = 0.0, b2 = 0.0;
    for (int b = 0; b < BB; b++) {
        const __half* p = g_o2h + (size_t)(b * CCH + c) * XLD;
        for (int m = t; m < NPIX; m += 256) {
            double v = (double)__half2float(p[m]);
            a  += v;
            b2 += v * v;
        }
    }
    s1[t] = a; s2[t] = b2; __syncthreads();
    for (int s = 128; s > 0; s >>= 1) {
        if (t < s) { s1[t] += s1[t + s]; s2[t] += s2[t + s]; }
        __syncthreads();
    }
    if (t == 0) {
        double cnt  = (double)(BB * NPIX);
        double mean = s1[0] / cnt;
        double var  = s2[0] / cnt - mean * mean;
        g_mean[c] = (float)mean;
        g_rstd[c] = (float)(1.0 / sqrt(var + (double)EPSV));
    }
}

// ---------------- BN apply + residual + ReLU ----------------
__global__ void epilogue_k(const float* __restrict__ bn_w,
                           const float* __restrict__ bn_b,
                           float* __restrict__ out)
{
    int idx = blockIdx.x * blockDim.x + threadIdx.x;
    if (idx >= BB*CCH*NPIX) return;
    int n  = idx % NPIX;
    int bc = idx / NPIX;
    int c  = bc % CCH;
    size_t off = (size_t)bc * XLD + n;
    float o = __half2float(g_o2h[off]);
    float v = (o - g_mean[c]) * g_rstd[c] * bn_w[c] + bn_b[c] + g_xp[off];
    out[idx] = fmaxf(v, 0.f);
}

// ---------------- launch ----------------
extern "C" void kernel_launch(void* const* d_in, const int* in_sizes, int n_in,
                              void* d_out, int out_size)
{
    const float* x       = (const float*)d_in[0];
    const float* theta_w = (const float*)d_in[1];
    const float* phi_w   = (const float*)d_in[2];
    const float* g_w     = (const float*)d_in[3];
    const float* y_w     = (const float*)d_in[4];
    const float* bn_w    = (const float*)d_in[5];
    const float* bn_b    = (const float*)d_in[6];
    float* out = (float*)d_out;

    cudaFuncSetAttribute(flash_k, cudaFuncAttributeMaxDynamicSharedMemorySize,
                         SMEM_FLASH);
    cudaFuncSetAttribute(projmma_k, cudaFuncAttributeMaxDynamicSharedMemorySize,
                         PJ_SMEM);
    cudaFuncSetAttribute(opmma_k, cudaFuncAttributeMaxDynamicSharedMemorySize,
                         PJ_SMEM);

    { int n = BB*CCH*NPIX; pool_k<<<(n + 255) / 256, 256>>>(x); }

    wsplit_k<<<512, 256>>>(theta_w, phi_w, g_w, y_w);

    { dim3 grid(32, 3, BB); projmma_k<<<grid, 256, PJ_SMEM>>>(); }

    { dim3 grid(32, BB); flash_k<<<grid, 256, SMEM_FLASH>>>(); }

    { dim3 grid(32, 2, BB); opmma_k<<<grid, 256, PJ_SMEM>>>(); }

    bnstats_k<<<CCH, 256>>>();

    { int n = BB*CCH*NPIX; epilogue_k<<<(n + 255) / 256, 256>>>(bn_w, bn_b, out); }
}

// round 17
// speedup vs baseline: 1.0484x; 1.0484x over previous
#include <cuda_runtime.h>
#include <cuda_bf16.h>
#include <cuda_fp16.h>
#include <math.h>
#include <stdint.h>

// ---------------- problem constants ----------------
#define BB    4
#define CCH   256
#define C2H   128
#define HO    63
#define WO    63
#define NPIX  (HO*WO)      // 3969
#define XLD   3972         // padded stride for xp/o2
#define XB    3976         // padded fp16 stride (16B-aligned rows)
#define YB    3976         // padded fp16 stride for y raw-view rows
#define MLD   4096         // fp16 m-stride for g (mult of 64)
#define HIN   128
#define WIN   128
#define EPSV  1e-5f
#define PAD   32768

// ---------------- scratch (device globals; zero-initialized) ----------------
__device__ __align__(256) float  g_xp [BB*CCH*XLD + PAD];   // residual fp32
__device__ __align__(256) __half g_o2h[BB*CCH*XLD + PAD];   // pre-BN fp16
__device__ float g_mean[CCH];
__device__ float g_rstd[CCH];

__device__ __align__(256) __half g_xph [BB*CCH*XB + PAD];  // xp fp16 (C-major rows)
__device__ __align__(256) __half g_thw [128*256];          // fp16 weights
__device__ __align__(256) __half g_phw [128*256];
__device__ __align__(256) __half g_gw  [128*256];
__device__ __align__(256) __half g_yw  [256*128];

__device__ __align__(256) __half g_th_h[BB*NPIX*C2H + PAD];   // theta (B,N,C2)
__device__ __align__(256) __half g_ph_h[BB*NPIX*C2H + PAD];   // phi   (B,M,C2)
__device__ __align__(256) __half g_gc_h[BB*C2H*MLD + PAD];    // g (B,C2,MLD) tail=0
__device__ __align__(256) __half g_yv_h[BB*C2H*YB + PAD];     // y raw-view (B,C2,m)

// ---------------- common asm helpers ----------------
#define MMAH16816(d, a, b)                                                  \
    asm volatile("mma.sync.aligned.m16n8k16.row.col.f32.f16.f16.f32 "       \
                 "{%0,%1,%2,%3},{%4,%5,%6,%7},{%8,%9},{%0,%1,%2,%3};"       \
                 : "+f"((d)[0]), "+f"((d)[1]), "+f"((d)[2]), "+f"((d)[3])   \
                 : "r"((a)[0]), "r"((a)[1]), "r"((a)[2]), "r"((a)[3]),      \
                   "r"((b)[0]), "r"((b)[1]))

#define LDSM4(r, p)                                                         \
    asm volatile("ldmatrix.sync.aligned.m8n8.x4.shared.b16 "                \
                 "{%0,%1,%2,%3}, [%4];"                                     \
                 : "=r"((r)[0]), "=r"((r)[1]), "=r"((r)[2]), "=r"((r)[3])   \
                 : "r"(p))

#define LDSM4T(r, p)                                                        \
    asm volatile("ldmatrix.sync.aligned.m8n8.x4.trans.shared.b16 "          \
                 "{%0,%1,%2,%3}, [%4];"                                     \
                 : "=r"((r)[0]), "=r"((r)[1]), "=r"((r)[2]), "=r"((r)[3])   \
                 : "r"(p))

#define CPA16(dst, src)                                                     \
    asm volatile("cp.async.cg.shared.global [%0], [%1], 16;"                \
                 :: "r"(dst), "l"(src) : "memory")

__device__ __forceinline__ uint32_t pk_h2(float x, float y) {
    __half2 h = __floats2half2_rn(x, y);
    return *(uint32_t*)&h;
}

// ---------------- 3x3/2 VALID max pool (+ fp16 emit) ----------------
__global__ void pool_k(const float* __restrict__ x) {
    int idx = blockIdx.x * blockDim.x + threadIdx.x;
    if (idx >= BB*CCH*NPIX) return;
    int n  = idx % NPIX;
    int bc = idx / NPIX;
    int ow = n % WO, oh = n / WO;
    const float* p = x + (size_t)bc * (HIN*WIN) + (oh*2) * WIN + (ow*2);
    float m = -INFINITY;
    #pragma unroll
    for (int i = 0; i < 3; i++) {
        m = fmaxf(m, p[i*WIN + 0]);
        m = fmaxf(m, p[i*WIN + 1]);
        m = fmaxf(m, p[i*WIN + 2]);
    }
    g_xp[(size_t)bc * XLD + n] = m;
    g_xph[(size_t)bc * XB + n] = __float2half(m);
}

// ---------------- weight fp16 prep ----------------
__global__ void wsplit_k(const float* __restrict__ thW, const float* __restrict__ phW,
                         const float* __restrict__ gW,  const float* __restrict__ yW) {
    int idx = blockIdx.x * blockDim.x + threadIdx.x;
    if (idx >= 4*32768) return;
    int arr = idx >> 15, off = idx & 32767;
    const float* s = (arr == 0) ? thW : (arr == 1) ? phW : (arr == 2) ? gW : yW;
    __half v = __float2half(s[off]);
    if      (arr == 0) g_thw[off] = v;
    else if (arr == 1) g_phw[off] = v;
    else if (arr == 2) g_gw [off] = v;
    else               g_yw [off] = v;
}

// ================ single-phase fp16 TN MMA for projections / outproj ================
#define PJ_SW  144
#define PJ_SX  272
#define PJ_WB  (128*PJ_SW)
#define PJ_XTB (64*PJ_SX)
#define PJ_STG (PJ_WB + PJ_XTB)
#define PJ_SMEM (2*PJ_STG)

__global__ __launch_bounds__(256) void projmma_k() {
    extern __shared__ __align__(256) char smem[];
    uint32_t sb = (uint32_t)__cvta_generic_to_shared(smem);
    int t = threadIdx.x, lane = t & 31, wid = t >> 5;
    int b = blockIdx.z, w = blockIdx.y;
    int j0 = blockIdx.x * 128;

    const __half* W  = (w == 0) ? g_thw : (w == 1) ? g_phw : g_gw;
    const __half* Xp = g_xph + (size_t)b * CCH * XB;

    int gq = lane >> 2, tg = lane & 3;
    int a_ro = (lane & 7) + ((lane >> 3) & 1) * 8;
    int a_co = (lane >> 4) * 8;
    int trow = (lane & 7) + ((lane >> 3) & 1) * 8;
    int tcol = (lane >> 4) * 8;

    float acc[16][4];
    #pragma unroll
    for (int fj = 0; fj < 16; fj++)
        #pragma unroll
        for (int e = 0; e < 4; e++) acc[fj][e] = 0.f;

    const int TOT = 4;
    auto issue = [&](int s) {
        int k0 = s * 64;
        uint32_t stg = sb + (s & 1) * PJ_STG;
        #pragma unroll
        for (int it = 0; it < 4; it++) {
            int cid = t + it * 256;
            int r = cid >> 3, q = cid & 7;
            CPA16(stg + r * PJ_SW + q * 16, W + r * 256 + k0 + q * 8);
        }
        #pragma unroll
        for (int it = 0; it < 4; it++) {
            int cid = t + it * 256;
            int r = cid >> 4, q = cid & 15;
            CPA16(stg + PJ_WB + r * PJ_SX + q * 16,
                  Xp + (size_t)(k0 + r) * XB + j0 + q * 8);
        }
        asm volatile("cp.async.commit_group;" ::: "memory");
    };
    issue(0);

    for (int s = 0; s < TOT; s++) {
        if (s + 1 < TOT) {
            issue(s + 1);
            asm volatile("cp.async.wait_group 1;" ::: "memory");
        } else {
            asm volatile("cp.async.wait_group 0;" ::: "memory");
        }
        __syncthreads();
        uint32_t stg = sb + (s & 1) * PJ_STG;
        uint32_t aB = stg + (wid * 16 + a_ro) * PJ_SW + a_co * 2;
        uint32_t xB = stg + PJ_WB + trow * PJ_SX + tcol * 2;
        #pragma unroll
        for (int k16 = 0; k16 < 4; k16++) {
            uint32_t a[4];
            LDSM4(a, aB + k16 * 32);
            #pragma unroll
            for (int jb = 0; jb < 8; jb++) {
                uint32_t r[4];
                LDSM4T(r, xB + k16 * 16 * PJ_SX + jb * 32);
                MMAH16816(acc[2*jb],     a, r);
                MMAH16816(acc[2*jb + 1], a, r + 2);
            }
        }
        __syncthreads();
    }

    if (w < 2) {
        float* stage = (float*)smem;
        int r0 = wid * 16 + gq, r1 = r0 + 8;
        #pragma unroll
        for (int fj = 0; fj < 16; fj++) {
            int c = fj * 8 + tg * 2;
            *(float2*)&stage[r0 * 132 + c] = make_float2(acc[fj][0], acc[fj][1]);
            *(float2*)&stage[r1 * 132 + c] = make_float2(acc[fj][2], acc[fj][3]);
        }
        __syncthreads();
        int j = t >> 1, half = t & 1;
        int n = j0 + j;
        if (n < NPIX) {
            size_t base = (size_t)(b * NPIX + n) * C2H + half * 64;
            __half* TH = ((w == 0) ? g_th_h : g_ph_h) + base;
            uint32_t hb[32];
            #pragma unroll
            for (int i = 0; i < 64; i += 2) {
                float v0 = stage[(half * 64 + i)     * 132 + j];
                float v1 = stage[(half * 64 + i + 1) * 132 + j];
                hb[i >> 1] = pk_h2(v0, v1);
            }
            #pragma unroll
            for (int u = 0; u < 8; u++)
                ((uint4*)TH)[u] = ((uint4*)hb)[u];
        }
    } else {
        int i0r = wid * 16 + gq;
        #pragma unroll
        for (int fj = 0; fj < 16; fj++) {
            int jj = j0 + fj * 8 + tg * 2;
            #pragma unroll
            for (int h = 0; h < 2; h++) {
                int i = i0r + h * 8;
                float v0 = acc[fj][2*h], v1 = acc[fj][2*h + 1];
                size_t base = (size_t)(b * C2H + i) * MLD + jj;
                if (jj + 1 < NPIX)
                    *(uint32_t*)(g_gc_h + base) = pk_h2(v0, v1);
                else if (jj < NPIX)
                    g_gc_h[base] = __float2half(v0);
            }
        }
    }
}

__global__ __launch_bounds__(256) void opmma_k() {
    extern __shared__ __align__(256) char smem[];
    uint32_t sb = (uint32_t)__cvta_generic_to_shared(smem);
    int t = threadIdx.x, lane = t & 31, wid = t >> 5;
    int b = blockIdx.z;
    int o0 = blockIdx.y * 128;
    int j0 = blockIdx.x * 128;

    const __half* Xp = g_yv_h + (size_t)b * C2H * YB;

    int gq = lane >> 2, tg = lane & 3;
    int a_ro = (lane & 7) + ((lane >> 3) & 1) * 8;
    int a_co = (lane >> 4) * 8;
    int trow = (lane & 7) + ((lane >> 3) & 1) * 8;
    int tcol = (lane >> 4) * 8;

    float acc[16][4];
    #pragma unroll
    for (int fj = 0; fj < 16; fj++)
        #pragma unroll
        for (int e = 0; e < 4; e++) acc[fj][e] = 0.f;

    const int TOT = 2;
    auto issue = [&](int s) {
        int k0 = s * 64;
        uint32_t stg = sb + (s & 1) * PJ_STG;
        #pragma unroll
        for (int it = 0; it < 4; it++) {
            int cid = t + it * 256;
            int r = cid >> 3, q = cid & 7;
            CPA16(stg + r * PJ_SW + q * 16, g_yw + (o0 + r) * 128 + k0 + q * 8);
        }
        #pragma unroll
        for (int it = 0; it < 4; it++) {
            int cid = t + it * 256;
            int r = cid >> 4, q = cid & 15;
            CPA16(stg + PJ_WB + r * PJ_SX + q * 16,
                  Xp + (size_t)(k0 + r) * YB + j0 + q * 8);
        }
        asm volatile("cp.async.commit_group;" ::: "memory");
    };
    issue(0);

    for (int s = 0; s < TOT; s++) {
        if (s + 1 < TOT) {
            issue(s + 1);
            asm volatile("cp.async.wait_group 1;" ::: "memory");
        } else {
            asm volatile("cp.async.wait_group 0;" ::: "memory");
        }
        __syncthreads();
        uint32_t stg = sb + (s & 1) * PJ_STG;
        uint32_t aB = stg + (wid * 16 + a_ro) * PJ_SW + a_co * 2;
        uint32_t xB = stg + PJ_WB + trow * PJ_SX + tcol * 2;
        #pragma unroll
        for (int k16 = 0; k16 < 4; k16++) {
            uint32_t a[4];
            LDSM4(a, aB + k16 * 32);
            #pragma unroll
            for (int jb = 0; jb < 8; jb++) {
                uint32_t r[4];
                LDSM4T(r, xB + k16 * 16 * PJ_SX + jb * 32);
                MMAH16816(acc[2*jb],     a, r);
                MMAH16816(acc[2*jb + 1], a, r + 2);
            }
        }
        __syncthreads();
    }

    int i0r = o0 + wid * 16 + gq;
    #pragma unroll
    for (int fj = 0; fj < 16; fj++) {
        int jj = j0 + fj * 8 + tg * 2;
        #pragma unroll
        for (int h = 0; h < 2; h++) {
            int i = i0r + h * 8;
            size_t base = (size_t)(b * CCH + i) * XLD + jj;
            if (jj + 1 < NPIX)
                *(uint32_t*)(g_o2h + base) = pk_h2(acc[fj][2*h], acc[fj][2*h + 1]);
            else if (jj < NPIX)
                g_o2h[base] = __float2half(acc[fj][2*h]);
        }
    }
}

// ============ fused flash attention: fp16 single-phase, 3-stage ring ============
#define TM   64
#define NT   63
#define THRB 272
#define GRB  144
#define SM_TH    0
#define SM_STG   34816
#define ST_PH    0
#define ST_G     17408
#define STG_SZ   35840
#define SMEM_FLASH (SM_STG + 3*STG_SZ)   // 142336

__global__ __launch_bounds__(256, 1) void flash_k() {
    extern __shared__ __align__(256) char smem[];
    uint32_t sb = (uint32_t)__cvta_generic_to_shared(smem);
    int t = threadIdx.x, lane = t & 31, wid = t >> 5;
    int b = blockIdx.y;
    int q0 = blockIdx.x * 128;

    #pragma unroll
    for (int it = 0; it < 8; it++) {
        int cid = t + it * 256;
        int r = cid >> 4, q = cid & 15;
        size_t off = (size_t)(b * NPIX + q0 + r) * C2H + q * 8;
        CPA16(sb + SM_TH + r * THRB + q * 16, g_th_h + off);
    }
    asm volatile("cp.async.commit_group;" ::: "memory");

    auto issue_stage = [&](int s) {
        int m0 = s * TM;
        uint32_t stg = sb + SM_STG + (s % 3) * STG_SZ;
        #pragma unroll
        for (int it = 0; it < 4; it++) {
            int cid = t + it * 256;
            int r = cid >> 4, q = cid & 15;
            size_t off = (size_t)(b * NPIX + m0 + r) * C2H + q * 8;
            CPA16(stg + ST_PH + r * THRB + q * 16, g_ph_h + off);
        }
        #pragma unroll
        for (int it = 0; it < 4; it++) {
            int cid = t + it * 256;
            int r = cid >> 3, q = cid & 7;
            size_t off = (size_t)(b * C2H + r) * MLD + m0 + q * 8;
            CPA16(stg + ST_G + r * GRB + q * 16, g_gc_h + off);
        }
        asm volatile("cp.async.commit_group;" ::: "memory");
    };
    issue_stage(0);

    int gq = lane >> 2, tg = lane & 3;
    int a_ro = (lane & 7) + ((lane >> 3) & 1) * 8;
    int a_co = (lane >> 4) * 8;
    int b_ro = (lane & 7) + ((lane >> 4) & 1) * 8;
    int b_co = ((lane >> 3) & 1) * 8;

    uint32_t thA = sb + SM_TH + (wid * 16 + a_ro) * THRB + a_co * 2;

    float m0r = -INFINITY, m1r = -INFINITY;
    float l0r = 0.f, l1r = 0.f;
    float accy[16][4];
    #pragma unroll
    for (int fc = 0; fc < 16; fc++)
        #pragma unroll
        for (int e = 0; e < 4; e++) accy[fc][e] = 0.f;

    for (int itr = 0; itr < NT; itr++) {
        if (itr + 1 < NT) {
            issue_stage(itr + 1);
            asm volatile("cp.async.wait_group 1;" ::: "memory");
        } else {
            asm volatile("cp.async.wait_group 0;" ::: "memory");
        }
        __syncthreads();    // single barrier/iter (3-stage ring makes tail sync unnecessary)
        uint32_t stg = sb + SM_STG + (itr % 3) * STG_SZ;

        // ---- score: single-phase fp16 ----
        float s[8][4];
        #pragma unroll
        for (int fj = 0; fj < 8; fj++)
            #pragma unroll
            for (int e = 0; e < 4; e++) s[fj][e] = 0.f;

        uint32_t bb = stg + ST_PH + b_ro * THRB + b_co * 2;
        #pragma unroll
        for (int k16 = 0; k16 < 8; k16++) {
            uint32_t a[4];
            LDSM4(a, thA + k16 * 32);
            #pragma unroll
            for (int mb = 0; mb < 4; mb++) {
                uint32_t r[4];
                LDSM4(r, bb + mb * 16 * THRB + k16 * 32);
                MMAH16816(s[2*mb],     a, r);
                MMAH16816(s[2*mb + 1], a, r + 2);
            }
        }

        if (itr == NT - 1) {
            int mbase = itr * TM;
            #pragma unroll
            for (int fj = 0; fj < 8; fj++) {
                int c = mbase + fj * 8 + tg * 2;
                if (c     >= NPIX) { s[fj][0] = -INFINITY; s[fj][2] = -INFINITY; }
                if (c + 1 >= NPIX) { s[fj][1] = -INFINITY; s[fj][3] = -INFINITY; }
            }
        }

        // ---- online softmax (R15 form) ----
        float mx0 = -INFINITY, mx1 = -INFINITY;
        #pragma unroll
        for (int fj = 0; fj < 8; fj++) {
            mx0 = fmaxf(mx0, fmaxf(s[fj][0], s[fj][1]));
            mx1 = fmaxf(mx1, fmaxf(s[fj][2], s[fj][3]));
        }
        mx0 = fmaxf(mx0, __shfl_xor_sync(~0u, mx0, 1));
        mx0 = fmaxf(mx0, __shfl_xor_sync(~0u, mx0, 2));
        mx1 = fmaxf(mx1, __shfl_xor_sync(~0u, mx1, 1));
        mx1 = fmaxf(mx1, __shfl_xor_sync(~0u, mx1, 2));

        float mn0 = fmaxf(m0r, mx0), mn1 = fmaxf(m1r, mx1);
        float sc0 = __expf(m0r - mn0), sc1 = __expf(m1r - mn1);
        m0r = mn0; m1r = mn1;

        uint32_t ph0[8], ph1[8];
        float sum0 = 0.f, sum1 = 0.f;
        #pragma unroll
        for (int fj = 0; fj < 8; fj++) {
            float p0 = __expf(s[fj][0] - mn0);
            float p1 = __expf(s[fj][1] - mn0);
            float p2 = __expf(s[fj][2] - mn1);
            float p3 = __expf(s[fj][3] - mn1);
            sum0 += p0 + p1; sum1 += p2 + p3;
            ph0[fj] = pk_h2(p0, p1);
            ph1[fj] = pk_h2(p2, p3);
        }
        sum0 += __shfl_xor_sync(~0u, sum0, 1);
        sum0 += __shfl_xor_sync(~0u, sum0, 2);
        sum1 += __shfl_xor_sync(~0u, sum1, 1);
        sum1 += __shfl_xor_sync(~0u, sum1, 2);
        l0r = l0r * sc0 + sum0;
        l1r = l1r * sc1 + sum1;

        #pragma unroll
        for (int fc = 0; fc < 16; fc++) {
            accy[fc][0] *= sc0; accy[fc][1] *= sc0;
            accy[fc][2] *= sc1; accy[fc][3] *= sc1;
        }

        // ---- AV: single-phase fp16 ----
        {
            uint32_t gb = stg + ST_G + b_ro * GRB + b_co * 2;
            #pragma unroll
            for (int kw = 0; kw < 4; kw++) {
                uint32_t a[4] = { ph0[2*kw], ph1[2*kw], ph0[2*kw+1], ph1[2*kw+1] };
                #pragma unroll
                for (int fc16 = 0; fc16 < 8; fc16++) {
                    uint32_t r[4];
                    LDSM4(r, gb + fc16 * 16 * GRB + kw * 32);
                    MMAH16816(accy[2*fc16],     a, r);
                    MMAH16816(accy[2*fc16 + 1], a, r + 2);
                }
            }
        }
        // no tail barrier: ring depth 3 guarantees safety (see theory)
    }

    // finalize: y /= l, emit raw-view (c, m) fp16
    float inv0 = 1.f / l0r, inv1 = 1.f / l1r;
    int row0 = q0 + wid * 16 + gq;
    int row1 = row0 + 8;
    auto emit = [&](int n, int cc, float v) {
        if (n >= NPIX) return;
        uint32_t q = (uint32_t)n * 128u + (uint32_t)cc;
        uint32_t c = q / 3969u;
        uint32_t m = q - c * 3969u;
        g_yv_h[(size_t)(b * C2H + c) * YB + m] = __float2half(v);
    };
    #pragma unroll
    for (int fc = 0; fc < 16; fc++) {
        int col = fc * 8 + tg * 2;
        emit(row0, col,     accy[fc][0] * inv0);
        emit(row0, col + 1, accy[fc][1] * inv0);
        emit(row1, col,     accy[fc][2] * inv1);
        emit(row1, col + 1, accy[fc][3] * inv1);
    }
}

// ---------------- BN stats (fp16 input) ----------------
__global__ void bnstats_k() {
    int c = blockIdx.x;
    int t = threadIdx.x;
    __shared__ double s1[256];
    __shared__ double s2[256];
    double a = 0.0, b2 = 0.0;
    for (int b = 0; b < BB; b++) {
        const __half* p = g_o2h + (size_t)(b * CCH + c) * XLD;
        for (int m = t; m < NPIX; m += 256) {
            double v = (double)__half2float(p[m]);
            a  += v;
            b2 += v * v;
        }
    }
    s1[t] = a; s2[t] = b2; __syncthreads();
    for (int s = 128; s > 0; s >>= 1) {
        if (t < s) { s1[t] += s1[t + s]; s2[t] += s2[t + s]; }
        __syncthreads();
    }
    if (t == 0) {
        double cnt  = (double)(BB * NPIX);
        double mean = s1[0] / cnt;
        double var  = s2[0] / cnt - mean * mean;
        g_mean[c] = (float)mean;
        g_rstd[c] = (float)(1.0 / sqrt(var + (double)EPSV));
    }
}

// ---------------- BN apply + residual + ReLU ----------------
__global__ void epilogue_k(const float* __restrict__ bn_w,
                           const float* __restrict__ bn_b,
                           float* __restrict__ out)
{
    int idx = blockIdx.x * blockDim.x + threadIdx.x;
    if (idx >= BB*CCH*NPIX) return;
    int n  = idx % NPIX;
    int bc = idx / NPIX;
    int c  = bc % CCH;
    size_t off = (size_t)bc * XLD + n;
    float o = __half2float(g_o2h[off]);
    float v = (o - g_mean[c]) * g_rstd[c] * bn_w[c] + bn_b[c] + g_xp[off];
    out[idx] = fmaxf(v, 0.f);
}

// ---------------- launch ----------------
extern "C" void kernel_launch(void* const* d_in, const int* in_sizes, int n_in,
                              void* d_out, int out_size)
{
    const float* x       = (const float*)d_in[0];
    const float* theta_w = (const float*)d_in[1];
    const float* phi_w   = (const float*)d_in[2];
    const float* g_w     = (const float*)d_in[3];
    const float* y_w     = (const float*)d_in[4];
    const float* bn_w    = (const float*)d_in[5];
    const float* bn_b    = (const float*)d_in[6];
    float* out = (float*)d_out;

    cudaFuncSetAttribute(flash_k, cudaFuncAttributeMaxDynamicSharedMemorySize,
                         SMEM_FLASH);
    cudaFuncSetAttribute(projmma_k, cudaFuncAttributeMaxDynamicSharedMemorySize,
                         PJ_SMEM);
    cudaFuncSetAttribute(opmma_k, cudaFuncAttributeMaxDynamicSharedMemorySize,
                         PJ_SMEM);

    { int n = BB*CCH*NPIX; pool_k<<<(n + 255) / 256, 256>>>(x); }

    wsplit_k<<<512, 256>>>(theta_w, phi_w, g_w, y_w);

    { dim3 grid(32, 3, BB); projmma_k<<<grid, 256, PJ_SMEM>>>(); }

    { dim3 grid(32, BB); flash_k<<<grid, 256, SMEM_FLASH>>>(); }

    { dim3 grid(32, 2, BB); opmma_k<<<grid, 256, PJ_SMEM>>>(); }

    bnstats_k<<<CCH, 256>>>();

    { int n = BB*CCH*NPIX; epilogue_k<<<(n + 255) / 256, 256>>>(bn_w, bn_b, out); }
}